// round 6
// baseline (speedup 1.0000x reference)
#include <cuda_runtime.h>
#include <cuda_fp16.h>
#include <math.h>
#include <stdint.h>

// ---------------- static config ----------------
#define TOK   100352          // 32 * 56 * 56 tokens
#define SCALE 0.17677669529663687f   // 32^-0.5

// ---------------- scratch (device globals; no allocs allowed) ----------------
__device__ __half g_ah[TOK * 256];     // LN1-window output (half); reused: attention out, LN2 out
__device__ __half g_qkvh[TOK * 768];   // QKV output (half)
__device__ __half g_hh[TOK * 1024];    // FC1/GELU output (half)
// transposed half weights: qkvT[768][256], projT[256][256], fc1T[1024][256], fc2T[256][1024]
__device__ __half g_wTh[196608 + 65536 + 262144 + 262144];
#define OFF_QKVT 0
#define OFF_PROJT 196608
#define OFF_FC1T 262144
#define OFF_FC2T 524288

// ---------------- helpers ----------------
__device__ __forceinline__ float gelu_exact(float x)
{
    return 0.5f * x * (1.0f + erff(x * 0.70710678118654752f));
}

__device__ __forceinline__ int unshift_row(int mr)
{
    int ntok = mr % 49; int wb = mr / 49;
    int wwi = wb & 7, wh = (wb >> 3) & 7, b = wb >> 6;
    int r = ntok / 7, c = ntok % 7;
    int oh = wh * 7 + r + 3; if (oh >= 56) oh -= 56;
    int ow = wwi * 7 + c + 3; if (ow >= 56) ow -= 56;
    return b * 3136 + oh * 56 + ow;
}

__device__ __forceinline__ void cpa16(uint32_t dst, const void* src)
{
    asm volatile("cp.async.cg.shared.global [%0], [%1], 16;" :: "r"(dst), "l"(src));
}

__device__ __forceinline__ void ldsm4(uint32_t addr, uint32_t& r0, uint32_t& r1,
                                      uint32_t& r2, uint32_t& r3)
{
    asm volatile("ldmatrix.sync.aligned.m8n8.x4.shared.b16 {%0,%1,%2,%3}, [%4];"
                 : "=r"(r0), "=r"(r1), "=r"(r2), "=r"(r3) : "r"(addr));
}

// ---------------- weight transpose + half round: in[K][N] -> out[N][K] ----------------
__global__ void transpose_half(const float* __restrict__ in, __half* __restrict__ out,
                               int K, int N)
{
    __shared__ float t[32][33];
    int bx = blockIdx.x * 32;   // n
    int by = blockIdx.y * 32;   // k
    int tx = threadIdx.x, ty = threadIdx.y;
#pragma unroll
    for (int i = 0; i < 32; i += 8)
        t[ty + i][tx] = in[(size_t)(by + ty + i) * N + bx + tx];
    __syncthreads();
#pragma unroll
    for (int i = 0; i < 32; i += 8)
        out[(size_t)(bx + ty + i) * K + by + tx] = __float2half_rn(t[tx][ty + i]);
}

// ---------------- LayerNorm (optionally fused with shift+window gather), half out ---------
template<bool WIN>
__global__ void ln_kernel(const float* __restrict__ in, const float* __restrict__ gm,
                          const float* __restrict__ bt, __half* __restrict__ out)
{
    int gw   = (blockIdx.x * blockDim.x + threadIdx.x) >> 5;
    int lane = threadIdx.x & 31;
    if (gw >= TOK) return;

    const float* src;
    if (WIN) src = in + (size_t)unshift_row(gw) * 256;
    else     src = in + (size_t)gw * 256;

    float v[8];
#pragma unroll
    for (int i = 0; i < 8; i++) v[i] = src[lane + 32 * i];

    float s = 0.f;
#pragma unroll
    for (int i = 0; i < 8; i++) s += v[i];
#pragma unroll
    for (int o = 16; o > 0; o >>= 1) s += __shfl_xor_sync(0xffffffffu, s, o);
    float mean = s * (1.0f / 256.0f);

    float q = 0.f;
#pragma unroll
    for (int i = 0; i < 8; i++) { float d = v[i] - mean; q += d * d; }
#pragma unroll
    for (int o = 16; o > 0; o >>= 1) q += __shfl_xor_sync(0xffffffffu, q, o);
    float rstd = rsqrtf(q * (1.0f / 256.0f) + 1e-5f);

    __half* orow = out + (size_t)gw * 256;
#pragma unroll
    for (int i = 0; i < 8; i++) {
        int cc = lane + 32 * i;
        orow[cc] = __float2half_rn((v[i] - mean) * rstd * gm[cc] + bt[cc]);
    }
}

// ---------------- fp16 tensor-core GEMM ----------------
// C[M,NN] = A[M,K] @ BT^T + epilogue   (A, BT half; BT is [NN][K])
// MODE 0: out = half(acc + bias)                            (QKV)
// MODE 1: out[dst] = res[dst] + acc + bias, dst = unshift   (proj + scatter + residual, f32)
// MODE 2: out = half(gelu(acc + bias))                      (FC1)
// MODE 3: out = res + acc + bias                            (FC2 + residual, f32)
//
// block 128x128, BK=64 halves (128B SW-swizzled rows), 8 warps (2x4), warp 64x32,
// mma m16n8k16 f16 with f32 accumulate, cp.async double buffer, ldmatrix.x4 frags.
template<int K, int NN, int MODE, typename OutT>
__global__ __launch_bounds__(256) void hgemm(
    const __half* __restrict__ A, const __half* __restrict__ BT,
    const float* __restrict__ bias, OutT* __restrict__ out,
    const float* __restrict__ res)
{
    extern __shared__ char smdyn[];
    const int tid  = threadIdx.x;
    const int lane = tid & 31;
    const int warp = tid >> 5;
    const int wm = warp >> 2, wn = warp & 3;     // 2 x 4 warp grid
    const int bm = blockIdx.y, bn = blockIdx.x;

    const uint32_t sbase = (uint32_t)__cvta_generic_to_shared(smdyn);
    // layout: A buffers at 0 / 16384, B buffers at 32768 / 49152 (16KB each)

    // staging: row = tid>>1 (0..127), granules (tid&1)*4 .. +3 (16B each)
    const int lr  = tid >> 1;
    const int lg0 = (tid & 1) * 4;
    const __half* Ag = A  + (size_t)(bm * 128 + lr) * K + lg0 * 8;
    const __half* Bg = BT + (size_t)(bn * 128 + lr) * K + lg0 * 8;
    const uint32_t rbase = (uint32_t)(lr * 128);
    const int r7 = lr & 7;

    float c[4][4][4];
#pragma unroll
    for (int i = 0; i < 4; i++)
#pragma unroll
        for (int j = 0; j < 4; j++)
#pragma unroll
            for (int l = 0; l < 4; l++) c[i][j][l] = 0.f;

#define PREF(KT, BUF)                                                           \
    do {                                                                        \
        const __half* _a = Ag + (KT) * 64;                                      \
        const __half* _b = Bg + (KT) * 64;                                      \
        uint32_t _oa = sbase + (BUF) * 16384;                                   \
        uint32_t _ob = sbase + 32768 + (BUF) * 16384;                           \
        _Pragma("unroll")                                                       \
        for (int i = 0; i < 4; i++) {                                           \
            uint32_t _sw = (uint32_t)(((lg0 + i) ^ r7) << 4);                   \
            cpa16(_oa + rbase + _sw, _a + i * 8);                               \
            cpa16(_ob + rbase + _sw, _b + i * 8);                               \
        }                                                                       \
        asm volatile("cp.async.commit_group;");                                 \
    } while (0)

    PREF(0, 0);
    asm volatile("cp.async.wait_group 0;");
    __syncthreads();

    // fragment row bases
    const int l7 = lane & 7;
    const int hiA = lane >> 4;            // A: granule bit from lane[4]
    const int hiB = (lane >> 3) & 1;      // B: granule bit from lane[3]
    uint32_t aRow[4], bRow[2];
#pragma unroll
    for (int mi = 0; mi < 4; mi++)
        aRow[mi] = sbase + (uint32_t)((wm * 64 + mi * 16 + (lane & 15)) * 128);
#pragma unroll
    for (int j = 0; j < 2; j++)
        bRow[j] = sbase + 32768 +
                  (uint32_t)((wn * 32 + j * 16 + l7 + 8 * (lane >> 4)) * 128);

    int buf = 0;
    const int KT = K / 64;
    for (int kt = 0; kt < KT; kt++) {
        if (kt + 1 < KT) PREF(kt + 1, buf ^ 1);
        const uint32_t boff = (uint32_t)(buf * 16384);
#pragma unroll
        for (int ks = 0; ks < 4; ks++) {
            const uint32_t gA = (uint32_t)((((2 * ks + hiA) ^ l7) << 4)) + boff;
            const uint32_t gB = (uint32_t)((((2 * ks + hiB) ^ l7) << 4)) + boff;
            uint32_t af[4][4], bq[2][4];
#pragma unroll
            for (int mi = 0; mi < 4; mi++)
                ldsm4(aRow[mi] + gA, af[mi][0], af[mi][1], af[mi][2], af[mi][3]);
#pragma unroll
            for (int j = 0; j < 2; j++)
                ldsm4(bRow[j] + gB, bq[j][0], bq[j][1], bq[j][2], bq[j][3]);
#pragma unroll
            for (int mi = 0; mi < 4; mi++)
#pragma unroll
                for (int ni = 0; ni < 4; ni++) {
                    asm volatile(
                        "mma.sync.aligned.m16n8k16.row.col.f32.f16.f16.f32 "
                        "{%0,%1,%2,%3}, {%4,%5,%6,%7}, {%8,%9}, {%0,%1,%2,%3};"
                        : "+f"(c[mi][ni][0]), "+f"(c[mi][ni][1]),
                          "+f"(c[mi][ni][2]), "+f"(c[mi][ni][3])
                        : "r"(af[mi][0]), "r"(af[mi][1]),
                          "r"(af[mi][2]), "r"(af[mi][3]),
                          "r"(bq[ni >> 1][(ni & 1) * 2]),
                          "r"(bq[ni >> 1][(ni & 1) * 2 + 1]));
                }
        }
        if (kt + 1 < KT) {
            asm volatile("cp.async.wait_group 0;");
            __syncthreads();
            buf ^= 1;
        }
    }
#undef PREF

    // ---- epilogue ----
    // C fragment: rows (lane>>2, +8), cols ni*8 + 2*(lane&3), +1
#pragma unroll
    for (int mi = 0; mi < 4; mi++) {
        int mr0 = bm * 128 + wm * 64 + mi * 16 + (lane >> 2);
        int mr1 = mr0 + 8;
        size_t dst0, dst1;
        if (MODE == 1) { dst0 = (size_t)unshift_row(mr0); dst1 = (size_t)unshift_row(mr1); }
        else           { dst0 = (size_t)mr0;              dst1 = (size_t)mr1; }
#pragma unroll
        for (int ni = 0; ni < 4; ni++) {
            int col = bn * 128 + wn * 32 + ni * 8 + 2 * (lane & 3);
            float2 bb = *(const float2*)&bias[col];
            float2 o0, o1;
            o0.x = c[mi][ni][0] + bb.x; o0.y = c[mi][ni][1] + bb.y;
            o1.x = c[mi][ni][2] + bb.x; o1.y = c[mi][ni][3] + bb.y;
            if (MODE == 1 || MODE == 3) {
                float2 r0v = *(const float2*)&res[dst0 * NN + col];
                float2 r1v = *(const float2*)&res[dst1 * NN + col];
                o0.x += r0v.x; o0.y += r0v.y;
                o1.x += r1v.x; o1.y += r1v.y;
            }
            if (MODE == 2) {
                o0.x = gelu_exact(o0.x); o0.y = gelu_exact(o0.y);
                o1.x = gelu_exact(o1.x); o1.y = gelu_exact(o1.y);
            }
            if (MODE == 0 || MODE == 2) {
                __half2* p0 = (__half2*)((__half*)out + dst0 * NN + col);
                __half2* p1 = (__half2*)((__half*)out + dst1 * NN + col);
                *p0 = __floats2half2_rn(o0.x, o0.y);
                *p1 = __floats2half2_rn(o1.x, o1.y);
            } else {
                *(float2*)((float*)out + dst0 * NN + col) = o0;
                *(float2*)((float*)out + dst1 * NN + col) = o1;
            }
        }
    }
}

// ---------------- windowed attention (one block per window-head) ----------------
__global__ __launch_bounds__(256) void attn_kernel(const __half* __restrict__ qkv,
                                                   const float* __restrict__ rpb,
                                                   __half* __restrict__ out)
{
    const int wb = blockIdx.x;
    const int h  = blockIdx.y;
    const int tid = threadIdx.x;

    __shared__ float qs[49 * 33];
    __shared__ float ks[49 * 33];
    __shared__ float vs[49 * 33];
    __shared__ float sc[49 * 49];
    __shared__ float rpb_s[169];
    __shared__ int   lab[49];

    for (int idx = tid; idx < 49 * 32; idx += 256) {
        int n = idx >> 5, d = idx & 31;
        size_t base = (size_t)(wb * 49 + n) * 768 + h * 32 + d;
        qs[n * 33 + d] = __half2float(qkv[base]) * SCALE;
        ks[n * 33 + d] = __half2float(qkv[base + 256]);
        vs[n * 33 + d] = __half2float(qkv[base + 512]);
    }
    for (int i = tid; i < 169; i += 256) rpb_s[i] = rpb[i * 8 + h];
    if (tid < 49) {
        int wwi = wb & 7, wh = (wb >> 3) & 7;
        int r = tid / 7, c = tid % 7;
        int gr = wh * 7 + r, gc = wwi * 7 + c;
        int lr = gr < 49 ? 0 : (gr < 53 ? 1 : 2);
        int lc = gc < 49 ? 0 : (gc < 53 ? 1 : 2);
        lab[tid] = lr * 3 + lc;
    }
    __syncthreads();

    for (int idx = tid; idx < 49 * 49; idx += 256) {
        int i = idx / 49, j = idx % 49;
        float s = 0.f;
#pragma unroll
        for (int d = 0; d < 32; d++) s += qs[i * 33 + d] * ks[j * 33 + d];
        int ri = i / 7, ci = i % 7, rj = j / 7, cj = j % 7;
        s += rpb_s[(ri - rj + 6) * 13 + (ci - cj + 6)];
        if (lab[i] != lab[j]) s -= 100.0f;
        sc[idx] = s;
    }
    __syncthreads();

    if (tid < 49) {
        float mx = -1e30f;
#pragma unroll 7
        for (int j = 0; j < 49; j++) mx = fmaxf(mx, sc[tid * 49 + j]);
        float sum = 0.f;
#pragma unroll 7
        for (int j = 0; j < 49; j++) {
            float e = __expf(sc[tid * 49 + j] - mx);
            sc[tid * 49 + j] = e;
            sum += e;
        }
        float inv = 1.0f / sum;
#pragma unroll 7
        for (int j = 0; j < 49; j++) sc[tid * 49 + j] *= inv;
    }
    __syncthreads();

    for (int idx = tid; idx < 49 * 32; idx += 256) {
        int i = idx >> 5, d = idx & 31;
        float o = 0.f;
#pragma unroll 7
        for (int j = 0; j < 49; j++) o += sc[i * 49 + j] * vs[j * 33 + d];
        out[(size_t)(wb * 49 + i) * 256 + h * 32 + d] = __float2half_rn(o);
    }
}

// ---------------- launch ----------------
extern "C" void kernel_launch(void* const* d_in, const int* in_sizes, int n_in,
                              void* d_out, int out_size)
{
    const float* x      = (const float*)d_in[0];
    const float* gamma1 = (const float*)d_in[1];
    const float* beta1  = (const float*)d_in[2];
    const float* qkv_w  = (const float*)d_in[3];
    const float* qkv_b  = (const float*)d_in[4];
    const float* proj_w = (const float*)d_in[5];
    const float* proj_b = (const float*)d_in[6];
    const float* rpb    = (const float*)d_in[7];
    const float* gamma2 = (const float*)d_in[8];
    const float* beta2  = (const float*)d_in[9];
    const float* fc1_w  = (const float*)d_in[10];
    const float* fc1_b  = (const float*)d_in[11];
    const float* fc2_w  = (const float*)d_in[12];
    const float* fc2_b  = (const float*)d_in[13];
    float* out = (float*)d_out;

    __half *pa, *pqkv, *ph, *pw;
    cudaGetSymbolAddress((void**)&pa, g_ah);
    cudaGetSymbolAddress((void**)&pqkv, g_qkvh);
    cudaGetSymbolAddress((void**)&ph, g_hh);
    cudaGetSymbolAddress((void**)&pw, g_wTh);

    const int DSMEM = 65536;
    cudaFuncSetAttribute(hgemm<256, 768, 0, __half>, cudaFuncAttributeMaxDynamicSharedMemorySize, DSMEM);
    cudaFuncSetAttribute(hgemm<256, 256, 1, float>,  cudaFuncAttributeMaxDynamicSharedMemorySize, DSMEM);
    cudaFuncSetAttribute(hgemm<256, 1024, 2, __half>, cudaFuncAttributeMaxDynamicSharedMemorySize, DSMEM);
    cudaFuncSetAttribute(hgemm<1024, 256, 3, float>, cudaFuncAttributeMaxDynamicSharedMemorySize, DSMEM);

    // 0. transpose + half-round weights
    transpose_half<<<dim3(768 / 32, 256 / 32), dim3(32, 8)>>>(qkv_w, pw + OFF_QKVT, 256, 768);
    transpose_half<<<dim3(256 / 32, 256 / 32), dim3(32, 8)>>>(proj_w, pw + OFF_PROJT, 256, 256);
    transpose_half<<<dim3(1024 / 32, 256 / 32), dim3(32, 8)>>>(fc1_w, pw + OFF_FC1T, 256, 1024);
    transpose_half<<<dim3(256 / 32, 1024 / 32), dim3(32, 8)>>>(fc2_w, pw + OFF_FC2T, 1024, 256);

    // 1. LN1 + cyclic shift + window partition -> g_ah (half)
    ln_kernel<true><<<TOK / 8, 256>>>(x, gamma1, beta1, pa);
    // 2. QKV GEMM -> g_qkvh (half)
    hgemm<256, 768, 0, __half><<<dim3(6, 784), 256, DSMEM>>>(pa, pw + OFF_QKVT, qkv_b, pqkv, nullptr);
    // 3. attention -> g_ah (reused, half)
    attn_kernel<<<dim3(2048, 8), 256>>>(pqkv, rpb, pa);
    // 4. proj GEMM + window reverse + roll scatter + residual -> d_out (f32)
    hgemm<256, 256, 1, float><<<dim3(2, 784), 256, DSMEM>>>(pa, pw + OFF_PROJT, proj_b, out, x);
    // 5. LN2 -> g_ah (reused, half)
    ln_kernel<false><<<TOK / 8, 256>>>(out, gamma2, beta2, pa);
    // 6. FC1 + GELU -> g_hh (half)
    hgemm<256, 1024, 2, __half><<<dim3(8, 784), 256, DSMEM>>>(pa, pw + OFF_FC1T, fc1_b, ph, nullptr);
    // 7. FC2 + residual -> d_out (f32)
    hgemm<1024, 256, 3, float><<<dim3(2, 784), 256, DSMEM>>>(ph, pw + OFF_FC2T, fc2_b, out, out);
    (void)in_sizes; (void)n_in; (void)out_size;
}

// round 7
// speedup vs baseline: 1.1063x; 1.1063x over previous
#include <cuda_runtime.h>
#include <math.h>
#include <stdint.h>

// ---------------- static config ----------------
#define TOK   100352          // 32 * 56 * 56 tokens
#define SCALE 0.17677669529663687f   // 32^-0.5

// ---------------- scratch (device globals; no allocs allowed) ----------------
__device__ float g_a[TOK * 256];      // LN1-window output; reused for attention output
__device__ float g_qkv[TOK * 768];    // QKV; reused for LN2 output
__device__ float g_h[TOK * 1024];     // FC1/GELU output
// transposed + tf32-rounded weights
__device__ float g_wT[196608 + 65536 + 262144 + 262144];
#define OFF_QKVT 0
#define OFF_PROJT 196608
#define OFF_FC1T 262144
#define OFF_FC2T 524288

// ---------------- helpers ----------------
__device__ __forceinline__ float tf32r(float x)
{
    uint32_t u;
    asm("cvt.rna.tf32.f32 %0, %1;" : "=r"(u) : "f"(x));
    return __uint_as_float(u);
}

__device__ __forceinline__ float gelu_exact(float x)
{
    return 0.5f * x * (1.0f + erff(x * 0.70710678118654752f));
}

__device__ __forceinline__ int unshift_row(int mr)
{
    int ntok = mr % 49; int wb = mr / 49;
    int wwi = wb & 7, wh = (wb >> 3) & 7, b = wb >> 6;
    int r = ntok / 7, c = ntok % 7;
    int oh = wh * 7 + r + 3; if (oh >= 56) oh -= 56;
    int ow = wwi * 7 + c + 3; if (ow >= 56) ow -= 56;
    return b * 3136 + oh * 56 + ow;
}

__device__ __forceinline__ void cpa16(uint32_t dst, const void* src)
{
    asm volatile("cp.async.cg.shared.global [%0], [%1], 16;" :: "r"(dst), "l"(src));
}

__device__ __forceinline__ void ldsm4(uint32_t addr, uint32_t& r0, uint32_t& r1,
                                      uint32_t& r2, uint32_t& r3)
{
    asm volatile("ldmatrix.sync.aligned.m8n8.x4.shared.b16 {%0,%1,%2,%3}, [%4];"
                 : "=r"(r0), "=r"(r1), "=r"(r2), "=r"(r3) : "r"(addr));
}

// ---------------- weight transpose + tf32 round: in[K][N] -> out[N][K] ----------------
__global__ void transpose_tf32(const float* __restrict__ in, float* __restrict__ out,
                               int K, int N)
{
    __shared__ float t[32][33];
    int bx = blockIdx.x * 32;   // n
    int by = blockIdx.y * 32;   // k
    int tx = threadIdx.x, ty = threadIdx.y;
#pragma unroll
    for (int i = 0; i < 32; i += 8)
        t[ty + i][tx] = in[(size_t)(by + ty + i) * N + bx + tx];
    __syncthreads();
#pragma unroll
    for (int i = 0; i < 32; i += 8)
        out[(size_t)(bx + ty + i) * K + by + tx] = tf32r(t[tx][ty + i]);
}

// ---------------- LayerNorm (optionally fused with shift+window gather) ----------------
template<bool WIN>
__global__ void ln_kernel(const float* __restrict__ in, const float* __restrict__ gm,
                          const float* __restrict__ bt, float* __restrict__ out)
{
    int gw   = (blockIdx.x * blockDim.x + threadIdx.x) >> 5;
    int lane = threadIdx.x & 31;
    if (gw >= TOK) return;

    const float* src;
    if (WIN) src = in + (size_t)unshift_row(gw) * 256;
    else     src = in + (size_t)gw * 256;

    float v[8];
#pragma unroll
    for (int i = 0; i < 8; i++) v[i] = src[lane + 32 * i];

    float s = 0.f;
#pragma unroll
    for (int i = 0; i < 8; i++) s += v[i];
#pragma unroll
    for (int o = 16; o > 0; o >>= 1) s += __shfl_xor_sync(0xffffffffu, s, o);
    float mean = s * (1.0f / 256.0f);

    float q = 0.f;
#pragma unroll
    for (int i = 0; i < 8; i++) { float d = v[i] - mean; q += d * d; }
#pragma unroll
    for (int o = 16; o > 0; o >>= 1) q += __shfl_xor_sync(0xffffffffu, q, o);
    float rstd = rsqrtf(q * (1.0f / 256.0f) + 1e-5f);

    float* orow = out + (size_t)gw * 256;
#pragma unroll
    for (int i = 0; i < 8; i++) {
        int cc = lane + 32 * i;
        orow[cc] = tf32r((v[i] - mean) * rstd * gm[cc] + bt[cc]);
    }
}

// ---------------- tf32 tensor-core GEMM (3-stage cp.async pipeline) ----------------
// C[M,NN] = A[M,K] @ BT^T + epilogue   (BT is [NN][K], tf32-rounded)
// MODE 0: out = acc + bias                                  (QKV)
// MODE 1: out[dst] = res[dst] + acc + bias, dst = unshift   (proj + scatter + residual)
// MODE 2: out = tf32r(gelu(acc + bias))                     (FC1)
// MODE 3: out = res + acc + bias                            (FC2 + residual)
//
// block 128x128, BK=32, 4 warps (2x2), warp 64x64, mma m16n8k8 tf32.
// smem: 3 stages x (A 16KB + B 16KB), 128B rows, XOR-swizzled, ldmatrix.x4 frags.
template<int K, int NN, int MODE>
__global__ __launch_bounds__(128) void mma_gemm(
    const float* __restrict__ A, const float* __restrict__ BT,
    const float* __restrict__ bias, float* __restrict__ out,
    const float* __restrict__ res)
{
    extern __shared__ float smdyn[];
    const int tid  = threadIdx.x;
    const int lane = tid & 31;
    const int warp = tid >> 5;
    const int wm = warp >> 1, wn = warp & 1;
    const int bm = blockIdx.y, bn = blockIdx.x;

    const uint32_t sbase = (uint32_t)__cvta_generic_to_shared(smdyn);
    // A stage s at sbase + s*16384 ; B stage s at sbase + 49152 + s*16384

    // staging thread mapping: 16 rows x 8 granules, 8 row-steps of 16
    const int lr = tid >> 3;   // 0..15
    const int lg = tid & 7;    // 0..7
    const uint32_t swz = (uint32_t)((lg ^ (lr & 7)) << 4);
    const float* Ag = A  + (size_t)(bm * 128 + lr) * K + lg * 4;
    const float* Bg = BT + (size_t)(bn * 128 + lr) * K + lg * 4;
    const uint32_t dA = sbase + lr * 128 + swz;
    const uint32_t dB = sbase + 49152 + lr * 128 + swz;

    float c[4][8][4];
#pragma unroll
    for (int i = 0; i < 4; i++)
#pragma unroll
        for (int j = 0; j < 8; j++)
#pragma unroll
            for (int l = 0; l < 4; l++) c[i][j][l] = 0.f;

    auto stage_fn = [&](int kt, int s) {
        const float* a = Ag + kt * 32;
        const float* b = Bg + kt * 32;
        const uint32_t off = (uint32_t)(s * 16384);
#pragma unroll
        for (int i = 0; i < 8; i++) {
            cpa16(dA + off + i * 2048, a + (size_t)i * 16 * K);
            cpa16(dB + off + i * 2048, b + (size_t)i * 16 * K);
        }
        asm volatile("cp.async.commit_group;");
    };

    stage_fn(0, 0);
    stage_fn(1, 1);

    // ldmatrix row bases (row&7 == lane&7 for all fragment rows)
    const int l15 = lane & 15, hi = lane >> 4, l7 = lane & 7;
    uint32_t aRow[4], bRow[4];
#pragma unroll
    for (int mi = 0; mi < 4; mi++) aRow[mi] = sbase + (uint32_t)((wm * 64 + mi * 16 + l15) * 128);
#pragma unroll
    for (int j = 0; j < 4; j++)    bRow[j]  = sbase + 49152 + (uint32_t)((wn * 64 + j * 16 + l15) * 128);

    const int KT = K / 32;
    int stg = 0;
#pragma unroll 1
    for (int kt = 0; kt < KT; kt++) {
        if (kt + 1 < KT) asm volatile("cp.async.wait_group 1;");
        else             asm volatile("cp.async.wait_group 0;");
        __syncthreads();
        if (kt + 2 < KT) {
            int s2 = stg + 2; if (s2 >= 3) s2 -= 3;
            stage_fn(kt + 2, s2);
        }
        const uint32_t soff = (uint32_t)(stg * 16384);
#pragma unroll
        for (int ks = 0; ks < 4; ks++) {
            const uint32_t gph = (uint32_t)(((2 * ks + hi) ^ l7) << 4) + soff;
            uint32_t af[4][4], bq[4][4];
#pragma unroll
            for (int mi = 0; mi < 4; mi++)
                ldsm4(aRow[mi] + gph, af[mi][0], af[mi][1], af[mi][2], af[mi][3]);
#pragma unroll
            for (int j = 0; j < 4; j++)
                ldsm4(bRow[j] + gph, bq[j][0], bq[j][1], bq[j][2], bq[j][3]);
#pragma unroll
            for (int mi = 0; mi < 4; mi++)
#pragma unroll
                for (int ni = 0; ni < 8; ni++) {
                    asm volatile(
                        "mma.sync.aligned.m16n8k8.row.col.f32.tf32.tf32.f32 "
                        "{%0,%1,%2,%3}, {%4,%5,%6,%7}, {%8,%9}, {%0,%1,%2,%3};"
                        : "+f"(c[mi][ni][0]), "+f"(c[mi][ni][1]),
                          "+f"(c[mi][ni][2]), "+f"(c[mi][ni][3])
                        : "r"(af[mi][0]), "r"(af[mi][1]),
                          "r"(af[mi][2]), "r"(af[mi][3]),
                          "r"(bq[ni >> 1][ni & 1]), "r"(bq[ni >> 1][2 + (ni & 1)]));
                }
        }
        if (++stg == 3) stg = 0;
    }

    // ---- epilogue ----
#pragma unroll
    for (int mi = 0; mi < 4; mi++) {
        int mr0 = bm * 128 + wm * 64 + mi * 16 + (lane >> 2);
        int mr1 = mr0 + 8;
        size_t dst0, dst1;
        if (MODE == 1) { dst0 = (size_t)unshift_row(mr0); dst1 = (size_t)unshift_row(mr1); }
        else           { dst0 = (size_t)mr0;              dst1 = (size_t)mr1; }
#pragma unroll
        for (int ni = 0; ni < 8; ni++) {
            int col = bn * 128 + wn * 64 + ni * 8 + 2 * (lane & 3);
            float2 bb = *(const float2*)&bias[col];
            float2 o0, o1;
            o0.x = c[mi][ni][0] + bb.x; o0.y = c[mi][ni][1] + bb.y;
            o1.x = c[mi][ni][2] + bb.x; o1.y = c[mi][ni][3] + bb.y;
            if (MODE == 1 || MODE == 3) {
                float2 r0v = *(const float2*)&res[dst0 * NN + col];
                float2 r1v = *(const float2*)&res[dst1 * NN + col];
                o0.x += r0v.x; o0.y += r0v.y;
                o1.x += r1v.x; o1.y += r1v.y;
            }
            if (MODE == 2) {
                o0.x = tf32r(gelu_exact(o0.x)); o0.y = tf32r(gelu_exact(o0.y));
                o1.x = tf32r(gelu_exact(o1.x)); o1.y = tf32r(gelu_exact(o1.y));
            }
            *(float2*)&out[dst0 * NN + col] = o0;
            *(float2*)&out[dst1 * NN + col] = o1;
        }
    }
}

// ---------------- windowed attention (register-blocked) ----------------
__global__ __launch_bounds__(256) void attn_kernel(const float* __restrict__ qkv,
                                                   const float* __restrict__ rpb,
                                                   float* __restrict__ out)
{
    const int wb = blockIdx.x;   // 0..2047
    const int h  = blockIdx.y;   // 0..7
    const int tid = threadIdx.x;

    __shared__ float qs[50 * 36];   // stride 36 (float4-aligned), padded row 49
    __shared__ float ks[50 * 36];
    __shared__ float vs[49 * 36];
    __shared__ float sc[49 * 49];
    __shared__ float rpb_s[169];
    __shared__ int   lab[49];

    for (int idx = tid; idx < 49 * 32; idx += 256) {
        int n = idx >> 5, d = idx & 31;
        size_t base = (size_t)(wb * 49 + n) * 768 + h * 32 + d;
        qs[n * 36 + d] = qkv[base] * SCALE;
        ks[n * 36 + d] = qkv[base + 256];
        vs[n * 36 + d] = qkv[base + 512];
    }
    if (tid < 32) { qs[49 * 36 + tid] = 0.f; ks[49 * 36 + tid] = 0.f; }  // pad row
    for (int i = tid; i < 169; i += 256) rpb_s[i] = rpb[i * 8 + h];
    if (tid < 49) {
        int wwi = wb & 7, wh = (wb >> 3) & 7;
        int r = tid / 7, c = tid % 7;
        int gr = wh * 7 + r, gc = wwi * 7 + c;
        int lr = gr < 49 ? 0 : (gr < 53 ? 1 : 2);
        int lc = gc < 49 ? 0 : (gc < 53 ? 1 : 2);
        lab[tid] = lr * 3 + lc;
    }
    __syncthreads();

    // scores: 2x2 register tiles over a 25x25 tile grid
    auto finish = [&](int i, int j, float s) {
        int ri = i / 7, ci = i % 7, rj = j / 7, cj = j % 7;
        s += rpb_s[(ri - rj + 6) * 13 + (ci - cj + 6)];
        if (lab[i] != lab[j]) s -= 100.0f;
        sc[i * 49 + j] = s;
    };
    for (int t = tid; t < 625; t += 256) {
        int ti = t / 25, tj = t % 25;
        int i0 = ti * 2, j0 = tj * 2;
        float s00 = 0.f, s01 = 0.f, s10 = 0.f, s11 = 0.f;
        const float* q0 = &qs[i0 * 36];
        const float* q1 = q0 + 36;
        const float* k0 = &ks[j0 * 36];
        const float* k1 = k0 + 36;
#pragma unroll
        for (int d = 0; d < 32; d += 4) {
            float4 a0 = *(const float4*)(q0 + d);
            float4 a1 = *(const float4*)(q1 + d);
            float4 b0 = *(const float4*)(k0 + d);
            float4 b1 = *(const float4*)(k1 + d);
            s00 += a0.x * b0.x + a0.y * b0.y + a0.z * b0.z + a0.w * b0.w;
            s01 += a0.x * b1.x + a0.y * b1.y + a0.z * b1.z + a0.w * b1.w;
            s10 += a1.x * b0.x + a1.y * b0.y + a1.z * b0.z + a1.w * b0.w;
            s11 += a1.x * b1.x + a1.y * b1.y + a1.z * b1.z + a1.w * b1.w;
        }
        bool iv = (i0 + 1 < 49), jv = (j0 + 1 < 49);
        finish(i0, j0, s00);
        if (jv) finish(i0, j0 + 1, s01);
        if (iv) finish(i0 + 1, j0, s10);
        if (iv && jv) finish(i0 + 1, j0 + 1, s11);
    }
    __syncthreads();

    // softmax: warp per row
    {
        int warp = tid >> 5, lane = tid & 31;
        for (int r = warp; r < 49; r += 8) {
            float v0 = sc[r * 49 + lane];
            float v1 = (lane + 32 < 49) ? sc[r * 49 + lane + 32] : -1e30f;
            float mx = fmaxf(v0, v1);
#pragma unroll
            for (int o = 16; o > 0; o >>= 1) mx = fmaxf(mx, __shfl_xor_sync(0xffffffffu, mx, o));
            float e0 = __expf(v0 - mx);
            float e1 = (lane + 32 < 49) ? __expf(v1 - mx) : 0.f;
            float sum = e0 + e1;
#pragma unroll
            for (int o = 16; o > 0; o >>= 1) sum += __shfl_xor_sync(0xffffffffu, sum, o);
            float inv = 1.0f / sum;
            sc[r * 49 + lane] = e0 * inv;
            if (lane + 32 < 49) sc[r * 49 + lane + 32] = e1 * inv;
        }
    }
    __syncthreads();

    // O = P @ V : thread computes (row i, 4 dims), float4 V loads
    for (int t = tid; t < 49 * 8; t += 256) {
        int i = t >> 3, dq = (t & 7) * 4;
        const float* sr = &sc[i * 49];
        float4 acc = make_float4(0.f, 0.f, 0.f, 0.f);
#pragma unroll 7
        for (int j = 0; j < 49; j++) {
            float p = sr[j];
            float4 v = *(const float4*)&vs[j * 36 + dq];
            acc.x += p * v.x; acc.y += p * v.y; acc.z += p * v.z; acc.w += p * v.w;
        }
        float4 o;
        o.x = tf32r(acc.x); o.y = tf32r(acc.y); o.z = tf32r(acc.z); o.w = tf32r(acc.w);
        *(float4*)&out[(size_t)(wb * 49 + i) * 256 + h * 32 + dq] = o;
    }
}

// ---------------- launch ----------------
extern "C" void kernel_launch(void* const* d_in, const int* in_sizes, int n_in,
                              void* d_out, int out_size)
{
    const float* x      = (const float*)d_in[0];
    const float* gamma1 = (const float*)d_in[1];
    const float* beta1  = (const float*)d_in[2];
    const float* qkv_w  = (const float*)d_in[3];
    const float* qkv_b  = (const float*)d_in[4];
    const float* proj_w = (const float*)d_in[5];
    const float* proj_b = (const float*)d_in[6];
    const float* rpb    = (const float*)d_in[7];
    const float* gamma2 = (const float*)d_in[8];
    const float* beta2  = (const float*)d_in[9];
    const float* fc1_w  = (const float*)d_in[10];
    const float* fc1_b  = (const float*)d_in[11];
    const float* fc2_w  = (const float*)d_in[12];
    const float* fc2_b  = (const float*)d_in[13];
    float* out = (float*)d_out;

    float *pa, *pqkv, *ph, *pw;
    cudaGetSymbolAddress((void**)&pa, g_a);
    cudaGetSymbolAddress((void**)&pqkv, g_qkv);
    cudaGetSymbolAddress((void**)&ph, g_h);
    cudaGetSymbolAddress((void**)&pw, g_wT);

    const int DSMEM = 98304;   // 3 stages x (16KB A + 16KB B)
    cudaFuncSetAttribute(mma_gemm<256, 768, 0>, cudaFuncAttributeMaxDynamicSharedMemorySize, DSMEM);
    cudaFuncSetAttribute(mma_gemm<256, 256, 1>, cudaFuncAttributeMaxDynamicSharedMemorySize, DSMEM);
    cudaFuncSetAttribute(mma_gemm<256, 1024, 2>, cudaFuncAttributeMaxDynamicSharedMemorySize, DSMEM);
    cudaFuncSetAttribute(mma_gemm<1024, 256, 3>, cudaFuncAttributeMaxDynamicSharedMemorySize, DSMEM);

    // 0. transpose + tf32-round weights
    transpose_tf32<<<dim3(768 / 32, 256 / 32), dim3(32, 8)>>>(qkv_w, pw + OFF_QKVT, 256, 768);
    transpose_tf32<<<dim3(256 / 32, 256 / 32), dim3(32, 8)>>>(proj_w, pw + OFF_PROJT, 256, 256);
    transpose_tf32<<<dim3(1024 / 32, 256 / 32), dim3(32, 8)>>>(fc1_w, pw + OFF_FC1T, 256, 1024);
    transpose_tf32<<<dim3(256 / 32, 1024 / 32), dim3(32, 8)>>>(fc2_w, pw + OFF_FC2T, 1024, 256);

    // 1. LN1 + cyclic shift + window partition -> g_a
    ln_kernel<true><<<TOK / 8, 256>>>(x, gamma1, beta1, pa);
    // 2. QKV GEMM -> g_qkv
    mma_gemm<256, 768, 0><<<dim3(6, 784), 128, DSMEM>>>(pa, pw + OFF_QKVT, qkv_b, pqkv, nullptr);
    // 3. attention -> g_a (reused)
    attn_kernel<<<dim3(2048, 8), 256>>>(pqkv, rpb, pa);
    // 4. proj GEMM + window reverse + roll scatter + residual -> d_out
    mma_gemm<256, 256, 1><<<dim3(2, 784), 128, DSMEM>>>(pa, pw + OFF_PROJT, proj_b, out, x);
    // 5. LN2 -> g_qkv (reused)
    ln_kernel<false><<<TOK / 8, 256>>>(out, gamma2, beta2, pqkv);
    // 6. FC1 + GELU -> g_h
    mma_gemm<256, 1024, 2><<<dim3(8, 784), 128, DSMEM>>>(pqkv, pw + OFF_FC1T, fc1_b, ph, nullptr);
    // 7. FC2 + residual -> d_out
    mma_gemm<1024, 256, 3><<<dim3(2, 784), 128, DSMEM>>>(ph, pw + OFF_FC2T, fc2_b, out, out);
    (void)in_sizes; (void)n_in; (void)out_size;
}